// round 6
// baseline (speedup 1.0000x reference)
#include <cuda_runtime.h>
#include <cuda_bf16.h>
#include <cstdint>
#include <cstddef>

#define N_NODES     100000
#define N_EDGES     800000
#define F           128
#define NUM_GRAPHS  128
#define NUM_CLASSES 10
#define BN_EPS      1e-5f

// ---------------- scratch (static device globals; no allocation) ----------------
__device__ float g_bufA[(size_t)N_NODES * F];   // 51.2 MB
__device__ float g_bufB[(size_t)N_NODES * F];   // 51.2 MB
__device__ float g_bufC[(size_t)N_NODES * F];   // 51.2 MB
__device__ float g_sum1[F];
__device__ float g_sq1[F];
__device__ float g_sum2[F];
__device__ float g_sq2[F];
__device__ float g_scale1[F];
__device__ float g_shift1[F];
__device__ float g_scale2[F];
__device__ float g_shift2[F];
__device__ float g_pooled[NUM_GRAPHS * F];
__device__ float g_counts[NUM_GRAPHS];
// pre-packed bf16 mma B-fragments for the 4 weight matrices (hi and lo split)
__device__ uint32_t g_wtabH[4][8192];
__device__ uint32_t g_wtabL[4][8192];

// ---------------- zero the small accumulators (every replay) --------------------
__global__ void zero_small_kernel() {
    int t = blockIdx.x * blockDim.x + threadIdx.x;
    if (t < F) {
        g_sum1[t] = 0.f; g_sq1[t] = 0.f;
        g_sum2[t] = 0.f; g_sq2[t] = 0.f;
    }
    if (t < NUM_GRAPHS) g_counts[t] = 0.f;
    for (int i = t; i < NUM_GRAPHS * F; i += blockDim.x * gridDim.x)
        g_pooled[i] = 0.f;
}

// ---------------- bf16 split helpers -------------------------------------------
__device__ __forceinline__ uint32_t pk2(__nv_bfloat16 a, __nv_bfloat16 b) {
    return (uint32_t)__bfloat16_as_ushort(b) << 16 | (uint32_t)__bfloat16_as_ushort(a);
}
__device__ __forceinline__ void split_pair(float x, float y,
                                           uint32_t& hi, uint32_t& lo) {
    __nv_bfloat16 hx = __float2bfloat16_rn(x);
    __nv_bfloat16 hy = __float2bfloat16_rn(y);
    float rx = x - __bfloat162float(hx);
    float ry = y - __bfloat162float(hy);
    hi = pk2(hx, hy);
    lo = pk2(__float2bfloat16_rn(rx), __float2bfloat16_rn(ry));
}

// ---------------- prep: pack all 4 W matrices into mma B-fragment tables --------
__global__ void prep_w_all_kernel(const float* __restrict__ Wa,
                                  const float* __restrict__ Wb,
                                  const float* __restrict__ Wc,
                                  const float* __restrict__ Wd) {
    int which = blockIdx.x >> 5;             // 32 blocks per matrix
    int tid   = (blockIdx.x & 31) * 256 + threadIdx.x;   // 0..8191
    const float* W = which == 0 ? Wa : which == 1 ? Wb : which == 2 ? Wc : Wd;
    int lane = tid & 31;
    int r    = (tid >> 5) & 1;
    int nt   = (tid >> 6) & 15;
    int kt   = tid >> 10;
    int k = kt * 16 + (lane & 3) * 2 + r * 8;
    int n = nt * 8 + (lane >> 2);
    float v0 = W[k * 128 + n];
    float v1 = W[(k + 1) * 128 + n];
    uint32_t hi, lo;
    split_pair(v0, v1, hi, lo);
    g_wtabH[which][tid] = hi;
    g_wtabL[which][tid] = lo;
}

// ---------------- mma wrapper ---------------------------------------------------
__device__ __forceinline__ void mma_bf16(float c[4],
                                         uint32_t a0, uint32_t a1, uint32_t a2, uint32_t a3,
                                         uint32_t b0, uint32_t b1) {
    asm volatile(
        "mma.sync.aligned.m16n8k16.row.col.f32.bf16.bf16.f32 "
        "{%0,%1,%2,%3}, {%4,%5,%6,%7}, {%8,%9}, {%0,%1,%2,%3};"
        : "+f"(c[0]), "+f"(c[1]), "+f"(c[2]), "+f"(c[3])
        : "r"(a0), "r"(a1), "r"(a2), "r"(a3), "r"(b0), "r"(b1));
}

// ---------------- fused MLP -----------------------------------------------------
// input per row = Ain[row] + (BN? relu(addSrc[row]*scale+shift) : addSrc[row])
// output C = relu(in@W1 + b1) @ W2 + b2 ; per-column BN stats (sum, sumsq) of the
// output are accumulated into gsum/gsq.
#define SA 68   // smem row stride in 32-bit words
#define MLP_SMEM (2 * 128 * SA * 4 + 256 * 4)   // A tiles + 256-float stats region
__global__ void __launch_bounds__(256, 2)
mlp_kernel(const float* __restrict__ Ain, const float* __restrict__ addSrc,
           const float* __restrict__ bnScale, const float* __restrict__ bnShift,
           float* __restrict__ C,
           const uint32_t* __restrict__ t1h, const uint32_t* __restrict__ t1l,
           const uint32_t* __restrict__ t2h, const uint32_t* __restrict__ t2l,
           const float* __restrict__ bias1, const float* __restrict__ bias2,
           float* __restrict__ gsum, float* __restrict__ gsq,
           int M) {
    extern __shared__ uint32_t sm[];
    uint32_t* Ahi = sm;                 // 128 * 68 words
    uint32_t* Alo = sm + 128 * SA;
    float*    Ssm = reinterpret_cast<float*>(sm + 2 * 128 * SA);  // [128] sums
    float*    Qsm = Ssm + 128;                                    // [128] sqs

    const int t    = threadIdx.x;
    const int lane = t & 31;
    const int w    = t >> 5;
    const int base = blockIdx.x * 128;

    if (t < 256) { Ssm[t] = 0.f; }   // zeros both Ssm and Qsm (256 contiguous)
    __syncthreads();

    // ---- stage A tile: (Ain + addSrc[BN]) fp32 -> bf16 hi/lo smem --------------
    {
        int r    = t >> 1;            // row 0..127 (warp w stages its own 16 rows)
        int half = t & 1;             // 64-col half
        int grow = base + r;
        bool valid = grow < M;
        const float4* src = valid
            ? reinterpret_cast<const float4*>(Ain + (size_t)grow * 128 + half * 64)
            : nullptr;
        const float4* add = valid
            ? reinterpret_cast<const float4*>(addSrc + (size_t)grow * 128 + half * 64)
            : nullptr;
        const float4* sc4 = bnScale
            ? reinterpret_cast<const float4*>(bnScale) + half * 16 : nullptr;
        const float4* sh4 = bnShift
            ? reinterpret_cast<const float4*>(bnShift) + half * 16 : nullptr;
        uint32_t* dh = Ahi + r * SA + half * 32;
        uint32_t* dl = Alo + r * SA + half * 32;
#pragma unroll
        for (int i = 0; i < 16; i++) {
            float4 v = make_float4(0.f, 0.f, 0.f, 0.f);
            if (valid) {
                float4 s = src[i];
                float4 a = add[i];
                if (sc4) {
                    float4 sc = sc4[i], sh = sh4[i];
                    a.x = fmaxf(a.x * sc.x + sh.x, 0.f);
                    a.y = fmaxf(a.y * sc.y + sh.y, 0.f);
                    a.z = fmaxf(a.z * sc.z + sh.z, 0.f);
                    a.w = fmaxf(a.w * sc.w + sh.w, 0.f);
                }
                v = make_float4(s.x + a.x, s.y + a.y, s.z + a.z, s.w + a.w);
            }
            uint32_t h0, l0, h1, l1;
            split_pair(v.x, v.y, h0, l0);
            split_pair(v.z, v.w, h1, l1);
            dh[i * 2]     = h0;  dl[i * 2]     = l0;
            dh[i * 2 + 1] = h1;  dl[i * 2 + 1] = l1;
        }
    }
    __syncwarp();

    const int m0   = w * 16;
    const int arow = m0 + (lane >> 2);
    const int acp  = lane & 3;

    float acc[16][4];
#pragma unroll
    for (int nt = 0; nt < 16; nt++)
#pragma unroll
        for (int i = 0; i < 4; i++) acc[nt][i] = 0.f;

    // ================= GEMM 1 =================
#pragma unroll
    for (int kt = 0; kt < 8; kt++) {
        int wp = arow * SA + kt * 8 + acp;
        uint32_t ah0 = Ahi[wp],     ah1 = Ahi[wp + 8 * SA];
        uint32_t ah2 = Ahi[wp + 4], ah3 = Ahi[wp + 8 * SA + 4];
        uint32_t al0 = Alo[wp],     al1 = Alo[wp + 8 * SA];
        uint32_t al2 = Alo[wp + 4], al3 = Alo[wp + 8 * SA + 4];
#pragma unroll
        for (int nt = 0; nt < 16; nt++) {
            int bi = (kt * 16 + nt) * 64 + lane;
            uint32_t bh0 = t1h[bi], bh1 = t1h[bi + 32];
            uint32_t bl0 = t1l[bi], bl1 = t1l[bi + 32];
            mma_bf16(acc[nt], ah0, ah1, ah2, ah3, bh0, bh1);
            mma_bf16(acc[nt], ah0, ah1, ah2, ah3, bl0, bl1);
            mma_bf16(acc[nt], al0, al1, al2, al3, bh0, bh1);
        }
    }
    __syncwarp();

    // ---- mid epilogue: bias1 + relu, re-split t1 into the same smem tile ----
#pragma unroll
    for (int nt = 0; nt < 16; nt++) {
        int n0 = nt * 8 + (lane & 3) * 2;
        float bb0 = bias1[n0], bb1 = bias1[n0 + 1];
        float v0 = fmaxf(acc[nt][0] + bb0, 0.f);
        float v1 = fmaxf(acc[nt][1] + bb1, 0.f);
        float v2 = fmaxf(acc[nt][2] + bb0, 0.f);
        float v3 = fmaxf(acc[nt][3] + bb1, 0.f);
        int word = (m0 + (lane >> 2)) * SA + nt * 4 + (lane & 3);
        uint32_t h, l;
        split_pair(v0, v1, h, l);
        Ahi[word] = h;  Alo[word] = l;
        split_pair(v2, v3, h, l);
        Ahi[word + 8 * SA] = h;  Alo[word + 8 * SA] = l;
#pragma unroll
        for (int i = 0; i < 4; i++) acc[nt][i] = 0.f;
    }
    __syncwarp();

    // ================= GEMM 2 =================
#pragma unroll
    for (int kt = 0; kt < 8; kt++) {
        int wp = arow * SA + kt * 8 + acp;
        uint32_t ah0 = Ahi[wp],     ah1 = Ahi[wp + 8 * SA];
        uint32_t ah2 = Ahi[wp + 4], ah3 = Ahi[wp + 8 * SA + 4];
        uint32_t al0 = Alo[wp],     al1 = Alo[wp + 8 * SA];
        uint32_t al2 = Alo[wp + 4], al3 = Alo[wp + 8 * SA + 4];
#pragma unroll
        for (int nt = 0; nt < 16; nt++) {
            int bi = (kt * 16 + nt) * 64 + lane;
            uint32_t bh0 = t2h[bi], bh1 = t2h[bi + 32];
            uint32_t bl0 = t2l[bi], bl1 = t2l[bi + 32];
            mma_bf16(acc[nt], ah0, ah1, ah2, ah3, bh0, bh1);
            mma_bf16(acc[nt], ah0, ah1, ah2, ah3, bl0, bl1);
            mma_bf16(acc[nt], al0, al1, al2, al3, bh0, bh1);
        }
    }

    // ---- final epilogue: bias2, fp32 store, fused per-column BN statistics ----
    int row0 = base + m0 + (lane >> 2);
    bool r0v = row0 < M, r1v = (row0 + 8) < M;
#pragma unroll
    for (int nt = 0; nt < 16; nt++) {
        int n0 = nt * 8 + (lane & 3) * 2;
        float bb0 = bias2[n0], bb1 = bias2[n0 + 1];
        float v0 = acc[nt][0] + bb0, v1 = acc[nt][1] + bb1;
        float v2 = acc[nt][2] + bb0, v3 = acc[nt][3] + bb1;
        if (r0v)
            *reinterpret_cast<float2*>(C + (size_t)row0 * 128 + n0) = make_float2(v0, v1);
        if (r1v)
            *reinterpret_cast<float2*>(C + (size_t)(row0 + 8) * 128 + n0) = make_float2(v2, v3);

        float s0 = (r0v ? v0 : 0.f) + (r1v ? v2 : 0.f);
        float s1 = (r0v ? v1 : 0.f) + (r1v ? v3 : 0.f);
        float q0 = (r0v ? v0 * v0 : 0.f) + (r1v ? v2 * v2 : 0.f);
        float q1 = (r0v ? v1 * v1 : 0.f) + (r1v ? v3 * v3 : 0.f);
#pragma unroll
        for (int o = 4; o < 32; o <<= 1) {
            s0 += __shfl_xor_sync(0xffffffffu, s0, o);
            s1 += __shfl_xor_sync(0xffffffffu, s1, o);
            q0 += __shfl_xor_sync(0xffffffffu, q0, o);
            q1 += __shfl_xor_sync(0xffffffffu, q1, o);
        }
        if ((lane >> 2) == 0) {   // lanes 0..3, distinct n0 per lane
            atomicAdd(&Ssm[n0], s0);     atomicAdd(&Ssm[n0 + 1], s1);
            atomicAdd(&Qsm[n0], q0);     atomicAdd(&Qsm[n0 + 1], q1);
        }
    }
    __syncthreads();
    if (t < 128) {
        atomicAdd(&gsum[t], Ssm[t]);
        atomicAdd(&gsq[t],  Qsm[t]);
    }
}

// ---------------- BN coefficient computation (1 block, 128 threads) -------------
__global__ void bn_coef_kernel(const float* __restrict__ sum,
                               const float* __restrict__ sq,
                               const float* __restrict__ gamma,
                               const float* __restrict__ beta,
                               float* __restrict__ scale,
                               float* __restrict__ shift) {
    int c = threadIdx.x;
    const float invN = 1.0f / (float)N_NODES;
    float mean = sum[c] * invN;
    float var  = fmaxf(sq[c] * invN - mean * mean, 0.f);
    float sc   = gamma[c] * rsqrtf(var + BN_EPS);
    scale[c] = sc;
    shift[c] = beta[c] - mean * sc;
}

// ---------------- edge scatter-add (plain): agg[dst] += X[src] ------------------
__global__ void scatter_kernel(const float* __restrict__ X,
                               const int* __restrict__ ei,
                               float* __restrict__ agg) {
    int widx = (int)(((size_t)blockIdx.x * blockDim.x + threadIdx.x) >> 5);
    int lane = threadIdx.x & 31;
    if (widx >= N_EDGES) return;
    int s = ei[widx];
    int d = ei[N_EDGES + widx];
    float4 v = reinterpret_cast<const float4*>(X + (size_t)s * F)[lane];
    atomicAdd(reinterpret_cast<float4*>(agg + (size_t)d * F) + lane, v);
}

// ---------------- edge scatter-add with on-the-fly BN+ReLU of the source -------
__global__ void scatter_bn_kernel(const float* __restrict__ X,
                                  const int* __restrict__ ei,
                                  float* __restrict__ agg,
                                  const float* __restrict__ scale,
                                  const float* __restrict__ shift) {
    int widx = (int)(((size_t)blockIdx.x * blockDim.x + threadIdx.x) >> 5);
    int lane = threadIdx.x & 31;
    if (widx >= N_EDGES) return;
    float4 sc = reinterpret_cast<const float4*>(scale)[lane];   // L1-resident
    float4 sh = reinterpret_cast<const float4*>(shift)[lane];
    int s = ei[widx];
    int d = ei[N_EDGES + widx];
    float4 v = reinterpret_cast<const float4*>(X + (size_t)s * F)[lane];
    v.x = fmaxf(v.x * sc.x + sh.x, 0.f);
    v.y = fmaxf(v.y * sc.y + sh.y, 0.f);
    v.z = fmaxf(v.z * sc.z + sh.z, 0.f);
    v.w = fmaxf(v.w * sc.w + sh.w, 0.f);
    atomicAdd(reinterpret_cast<float4*>(agg + (size_t)d * F) + lane, v);
}

// ---------------- fused BN2 + ReLU + segmented pool + counts (batch sorted) -----
#define POOL_CHUNK 512
__global__ void pool_kernel(const float* __restrict__ H,
                            const float* __restrict__ scale,
                            const float* __restrict__ shift,
                            const int* __restrict__ batch) {
    const int c = threadIdx.x;   // blockDim = 128
    float sc = scale[c], sh = shift[c];

    int r0 = blockIdx.x * POOL_CHUNK;
    if (r0 >= N_NODES) return;
    int r1 = min(r0 + POOL_CHUNK, N_NODES);

    int g = batch[r0];
    float acc = 0.f;
    int cnt = 0;
    for (int r = r0; r < r1; r++) {
        int gg = batch[r];
        if (gg != g) {
            atomicAdd(&g_pooled[g * F + c], acc);
            if (c == 0) atomicAdd(&g_counts[g], (float)cnt);
            acc = 0.f; cnt = 0; g = gg;
        }
        acc += fmaxf(H[(size_t)r * F + c] * sc + sh, 0.f);
        cnt++;
    }
    atomicAdd(&g_pooled[g * F + c], acc);
    if (c == 0) atomicAdd(&g_counts[g], (float)cnt);
}

// ---------------- head: mean-pool divide + linear + log_softmax ----------------
__global__ void head_kernel(const float* __restrict__ Wlin,
                            const float* __restrict__ blin,
                            float* __restrict__ out) {
    __shared__ float Ws[F * NUM_CLASSES];
    int t = threadIdx.x;   // blockDim = 128, one thread per graph
    for (int i = t; i < F * NUM_CLASSES; i += 128) Ws[i] = Wlin[i];
    __syncthreads();

    int g = t;
    float inv = 1.0f / fmaxf(g_counts[g], 1.0f);
    float logit[NUM_CLASSES];
#pragma unroll
    for (int j = 0; j < NUM_CLASSES; j++) logit[j] = blin[j];
    for (int c = 0; c < F; c++) {
        float p = g_pooled[g * F + c] * inv;
#pragma unroll
        for (int j = 0; j < NUM_CLASSES; j++)
            logit[j] += p * Ws[c * NUM_CLASSES + j];
    }
    float m = logit[0];
#pragma unroll
    for (int j = 1; j < NUM_CLASSES; j++) m = fmaxf(m, logit[j]);
    float se = 0.f;
#pragma unroll
    for (int j = 0; j < NUM_CLASSES; j++) se += expf(logit[j] - m);
    float lse = logf(se);
#pragma unroll
    for (int j = 0; j < NUM_CLASSES; j++)
        out[g * NUM_CLASSES + j] = logit[j] - m - lse;
}

// ================================================================================
extern "C" void kernel_launch(void* const* d_in, const int* in_sizes, int n_in,
                              void* d_out, int out_size) {
    const float* x     = (const float*)d_in[0];
    const int*   ei    = (const int*)d_in[1];
    const int*   batch = (const int*)d_in[2];
    const float* W1a = (const float*)d_in[3];
    const float* b1a = (const float*)d_in[4];
    const float* W1b = (const float*)d_in[5];
    const float* b1b = (const float*)d_in[6];
    const float* gamma1 = (const float*)d_in[7];
    const float* beta1  = (const float*)d_in[8];
    const float* W2a = (const float*)d_in[9];
    const float* b2a = (const float*)d_in[10];
    const float* W2b = (const float*)d_in[11];
    const float* b2b = (const float*)d_in[12];
    const float* gamma2 = (const float*)d_in[13];
    const float* beta2  = (const float*)d_in[14];
    const float* Wlin = (const float*)d_in[15];
    const float* blin = (const float*)d_in[16];
    float* out = (float*)d_out;

    float *pA, *pB, *pC, *pSum1, *pSq1, *pSum2, *pSq2;
    float *pScale1, *pShift1, *pScale2, *pShift2;
    uint32_t *pWH, *pWL;
    cudaGetSymbolAddress((void**)&pA, g_bufA);
    cudaGetSymbolAddress((void**)&pB, g_bufB);
    cudaGetSymbolAddress((void**)&pC, g_bufC);
    cudaGetSymbolAddress((void**)&pSum1, g_sum1);
    cudaGetSymbolAddress((void**)&pSq1,  g_sq1);
    cudaGetSymbolAddress((void**)&pSum2, g_sum2);
    cudaGetSymbolAddress((void**)&pSq2,  g_sq2);
    cudaGetSymbolAddress((void**)&pScale1, g_scale1);
    cudaGetSymbolAddress((void**)&pShift1, g_shift1);
    cudaGetSymbolAddress((void**)&pScale2, g_scale2);
    cudaGetSymbolAddress((void**)&pShift2, g_shift2);
    cudaGetSymbolAddress((void**)&pWH, g_wtabH);
    cudaGetSymbolAddress((void**)&pWL, g_wtabL);

    static int smem_set = 0;
    if (!smem_set) {
        cudaFuncSetAttribute(mlp_kernel,
                             cudaFuncAttributeMaxDynamicSharedMemorySize, MLP_SMEM);
        smem_set = 1;
    }

    const int M = N_NODES;
    const int mlpBlocks = (M + 127) / 128;
    const int scatterBlocks = (N_EDGES * 32) / 256;
    const size_t bufBytes = (size_t)N_NODES * F * sizeof(float);

    // prep: zero accumulators, pack weight tables, zero agg1
    zero_small_kernel<<<64, 256>>>();
    prep_w_all_kernel<<<128, 256>>>(W1a, W1b, W2a, W2b);
    cudaMemsetAsync(pA, 0, bufBytes);

    // ---- layer 1: agg1(scatter part) -> bufA ; MLP1 adds +x during staging
    scatter_kernel<<<scatterBlocks, 256>>>(x, ei, pA);
    mlp_kernel<<<mlpBlocks, 256, MLP_SMEM>>>(
        pA, x, nullptr, nullptr, pA,
        pWH + 0 * 8192, pWL + 0 * 8192, pWH + 1 * 8192, pWL + 1 * 8192,
        b1a, b1b, pSum1, pSq1, M);
    bn_coef_kernel<<<1, 128>>>(pSum1, pSq1, gamma1, beta1, pScale1, pShift1);

    // ---- layer 2: scatter of BN1(h1) -> bufC ; MLP2 adds +BN1(h1) during staging
    cudaMemsetAsync(pC, 0, bufBytes);
    scatter_bn_kernel<<<scatterBlocks, 256>>>(pA, ei, pC, pScale1, pShift1);
    mlp_kernel<<<mlpBlocks, 256, MLP_SMEM>>>(
        pC, pA, pScale1, pShift1, pB,
        pWH + 2 * 8192, pWL + 2 * 8192, pWH + 3 * 8192, pWL + 3 * 8192,
        b2a, b2b, pSum2, pSq2, M);
    bn_coef_kernel<<<1, 128>>>(pSum2, pSq2, gamma2, beta2, pScale2, pShift2);

    // ---- pooling (BN2+ReLU on the fly, fused counts) + head
    pool_kernel<<<(N_NODES + POOL_CHUNK - 1) / POOL_CHUNK, 128>>>(
        pB, pScale2, pShift2, batch);
    head_kernel<<<1, 128>>>(Wlin, blin, out);
}

// round 7
// speedup vs baseline: 1.0112x; 1.0112x over previous
#include <cuda_runtime.h>
#include <cuda_bf16.h>
#include <cstdint>
#include <cstddef>

#define N_NODES     100000
#define N_EDGES     800000
#define F           128
#define NUM_GRAPHS  128
#define NUM_CLASSES 10
#define BN_EPS      1e-5f

// ---------------- scratch (static device globals; no allocation) ----------------
__device__ float g_bufA[(size_t)N_NODES * F];   // 51.2 MB
__device__ float g_bufB[(size_t)N_NODES * F];   // 51.2 MB
__device__ float g_bufC[(size_t)N_NODES * F];   // 51.2 MB
__device__ float g_sum1[F];
__device__ float g_sq1[F];
__device__ float g_sum2[F];
__device__ float g_sq2[F];
__device__ float g_scale1[F];
__device__ float g_shift1[F];
__device__ float g_scale2[F];
__device__ float g_shift2[F];
__device__ float g_pooled[NUM_GRAPHS * F];
__device__ float g_counts[NUM_GRAPHS];
// packed bf16 mma B-fragments: per (matrix, kt*16+nt, lane) one uint4 {h0,h1,l0,l1}
__device__ uint4 g_wtabP[4][4096];

// ---------------- zero the small accumulators (every replay) --------------------
__global__ void zero_small_kernel() {
    int t = blockIdx.x * blockDim.x + threadIdx.x;
    if (t < F) {
        g_sum1[t] = 0.f; g_sq1[t] = 0.f;
        g_sum2[t] = 0.f; g_sq2[t] = 0.f;
    }
    if (t < NUM_GRAPHS) g_counts[t] = 0.f;
    for (int i = t; i < NUM_GRAPHS * F; i += blockDim.x * gridDim.x)
        g_pooled[i] = 0.f;
}

// ---------------- bf16 split helpers -------------------------------------------
__device__ __forceinline__ uint32_t pk2(__nv_bfloat16 a, __nv_bfloat16 b) {
    return (uint32_t)__bfloat16_as_ushort(b) << 16 | (uint32_t)__bfloat16_as_ushort(a);
}
__device__ __forceinline__ void split_pair(float x, float y,
                                           uint32_t& hi, uint32_t& lo) {
    __nv_bfloat16 hx = __float2bfloat16_rn(x);
    __nv_bfloat16 hy = __float2bfloat16_rn(y);
    float rx = x - __bfloat162float(hx);
    float ry = y - __bfloat162float(hy);
    hi = pk2(hx, hy);
    lo = pk2(__float2bfloat16_rn(rx), __float2bfloat16_rn(ry));
}

// ---------------- prep: pack all 4 W matrices into packed uint4 fragment tables -
// entry e = kt*16+nt (kt outer), lane: element (k,n):
//   n = nt*8 + (lane>>2) ; k0 = kt*16 + (lane&3)*2 ; second reg at k0+8
__global__ void prep_w_all_kernel(const float* __restrict__ Wa,
                                  const float* __restrict__ Wb,
                                  const float* __restrict__ Wc,
                                  const float* __restrict__ Wd) {
    int gid   = blockIdx.x * blockDim.x + threadIdx.x;   // 0..16383
    int which = gid >> 12;
    int tid   = gid & 4095;
    const float* W = which == 0 ? Wa : which == 1 ? Wb : which == 2 ? Wc : Wd;
    int lane = tid & 31;
    int e    = tid >> 5;
    int nt   = e & 15;
    int kt   = e >> 4;
    int n  = nt * 8 + (lane >> 2);
    int k0 = kt * 16 + (lane & 3) * 2;
    uint32_t h0, l0, h1, l1;
    split_pair(W[k0 * 128 + n],       W[(k0 + 1) * 128 + n], h0, l0);
    split_pair(W[(k0 + 8) * 128 + n], W[(k0 + 9) * 128 + n], h1, l1);
    g_wtabP[which][tid] = make_uint4(h0, h1, l0, l1);
}

// ---------------- mma wrapper ---------------------------------------------------
__device__ __forceinline__ void mma_bf16(float c[4],
                                         uint32_t a0, uint32_t a1, uint32_t a2, uint32_t a3,
                                         uint32_t b0, uint32_t b1) {
    asm volatile(
        "mma.sync.aligned.m16n8k16.row.col.f32.bf16.bf16.f32 "
        "{%0,%1,%2,%3}, {%4,%5,%6,%7}, {%8,%9}, {%0,%1,%2,%3};"
        : "+f"(c[0]), "+f"(c[1]), "+f"(c[2]), "+f"(c[3])
        : "r"(a0), "r"(a1), "r"(a2), "r"(a3), "r"(b0), "r"(b1));
}

// ---------------- fused MLP -----------------------------------------------------
// input per row = Ain[row] + (BN? relu(addSrc[row]*scale+shift) : addSrc[row])
// output C = relu(in@W1 + b1) @ W2 + b2 ; per-column BN stats of the output
// accumulated into gsum/gsq.
#define SA 68   // smem row stride in 32-bit words
#define MLP_SMEM (2 * 128 * SA * 4 + 256 * 4)   // A tiles + 256-float stats region
__global__ void __launch_bounds__(256, 2)
mlp_kernel(const float* __restrict__ Ain, const float* __restrict__ addSrc,
           const float* __restrict__ bnScale, const float* __restrict__ bnShift,
           float* __restrict__ C,
           const uint4* __restrict__ t1p, const uint4* __restrict__ t2p,
           const float* __restrict__ bias1, const float* __restrict__ bias2,
           float* __restrict__ gsum, float* __restrict__ gsq,
           int M) {
    extern __shared__ uint32_t sm[];
    uint32_t* Ahi = sm;                 // 128 * 68 words
    uint32_t* Alo = sm + 128 * SA;
    float*    Ssm = reinterpret_cast<float*>(sm + 2 * 128 * SA);  // [128] sums
    float*    Qsm = Ssm + 128;                                    // [128] sqs

    const int t    = threadIdx.x;
    const int lane = t & 31;
    const int w    = t >> 5;
    const int base = blockIdx.x * 128;

    if (t < 256) { Ssm[t] = 0.f; }   // zeros both Ssm and Qsm (256 contiguous)
    __syncthreads();

    // ---- stage A tile: (Ain + addSrc[BN]) fp32 -> bf16 hi/lo smem --------------
    {
        int r    = t >> 1;            // row 0..127 (warp w stages its own 16 rows)
        int half = t & 1;             // 64-col half
        int grow = base + r;
        bool valid = grow < M;
        const float4* src = valid
            ? reinterpret_cast<const float4*>(Ain + (size_t)grow * 128 + half * 64)
            : nullptr;
        const float4* add = valid
            ? reinterpret_cast<const float4*>(addSrc + (size_t)grow * 128 + half * 64)
            : nullptr;
        const float4* sc4 = bnScale
            ? reinterpret_cast<const float4*>(bnScale) + half * 16 : nullptr;
        const float4* sh4 = bnShift
            ? reinterpret_cast<const float4*>(bnShift) + half * 16 : nullptr;
        uint32_t* dh = Ahi + r * SA + half * 32;
        uint32_t* dl = Alo + r * SA + half * 32;
#pragma unroll
        for (int i = 0; i < 16; i++) {
            float4 v = make_float4(0.f, 0.f, 0.f, 0.f);
            if (valid) {
                float4 s = src[i];
                float4 a = add[i];
                if (sc4) {
                    float4 sc = sc4[i], sh = sh4[i];
                    a.x = fmaxf(a.x * sc.x + sh.x, 0.f);
                    a.y = fmaxf(a.y * sc.y + sh.y, 0.f);
                    a.z = fmaxf(a.z * sc.z + sh.z, 0.f);
                    a.w = fmaxf(a.w * sc.w + sh.w, 0.f);
                }
                v = make_float4(s.x + a.x, s.y + a.y, s.z + a.z, s.w + a.w);
            }
            uint32_t h0, l0, h1, l1;
            split_pair(v.x, v.y, h0, l0);
            split_pair(v.z, v.w, h1, l1);
            dh[i * 2]     = h0;  dl[i * 2]     = l0;
            dh[i * 2 + 1] = h1;  dl[i * 2 + 1] = l1;
        }
    }
    __syncwarp();

    const int m0   = w * 16;
    const int arow = m0 + (lane >> 2);
    const int acp  = lane & 3;

    float acc[16][4];
#pragma unroll
    for (int nt = 0; nt < 16; nt++)
#pragma unroll
        for (int i = 0; i < 4; i++) acc[nt][i] = 0.f;

    // ================= GEMM 1 =================
#pragma unroll
    for (int kt = 0; kt < 8; kt++) {
        int wp = arow * SA + kt * 8 + acp;
        uint32_t ah0 = Ahi[wp],     ah1 = Ahi[wp + 8 * SA];
        uint32_t ah2 = Ahi[wp + 4], ah3 = Ahi[wp + 8 * SA + 4];
        uint32_t al0 = Alo[wp],     al1 = Alo[wp + 8 * SA];
        uint32_t al2 = Alo[wp + 4], al3 = Alo[wp + 8 * SA + 4];
#pragma unroll
        for (int nt = 0; nt < 16; nt++) {
            uint4 b = t1p[(kt * 16 + nt) * 32 + lane];
            mma_bf16(acc[nt], ah0, ah1, ah2, ah3, b.x, b.y);   // hi*hi
            mma_bf16(acc[nt], ah0, ah1, ah2, ah3, b.z, b.w);   // hi*lo
            mma_bf16(acc[nt], al0, al1, al2, al3, b.x, b.y);   // lo*hi
        }
    }
    __syncwarp();

    // ---- mid epilogue: bias1 + relu, re-split t1 into the same smem tile ----
#pragma unroll
    for (int nt = 0; nt < 16; nt++) {
        int n0 = nt * 8 + (lane & 3) * 2;
        float bb0 = bias1[n0], bb1 = bias1[n0 + 1];
        float v0 = fmaxf(acc[nt][0] + bb0, 0.f);
        float v1 = fmaxf(acc[nt][1] + bb1, 0.f);
        float v2 = fmaxf(acc[nt][2] + bb0, 0.f);
        float v3 = fmaxf(acc[nt][3] + bb1, 0.f);
        int word = (m0 + (lane >> 2)) * SA + nt * 4 + (lane & 3);
        uint32_t h, l;
        split_pair(v0, v1, h, l);
        Ahi[word] = h;  Alo[word] = l;
        split_pair(v2, v3, h, l);
        Ahi[word + 8 * SA] = h;  Alo[word + 8 * SA] = l;
#pragma unroll
        for (int i = 0; i < 4; i++) acc[nt][i] = 0.f;
    }
    __syncwarp();

    // ================= GEMM 2 =================
#pragma unroll
    for (int kt = 0; kt < 8; kt++) {
        int wp = arow * SA + kt * 8 + acp;
        uint32_t ah0 = Ahi[wp],     ah1 = Ahi[wp + 8 * SA];
        uint32_t ah2 = Ahi[wp + 4], ah3 = Ahi[wp + 8 * SA + 4];
        uint32_t al0 = Alo[wp],     al1 = Alo[wp + 8 * SA];
        uint32_t al2 = Alo[wp + 4], al3 = Alo[wp + 8 * SA + 4];
#pragma unroll
        for (int nt = 0; nt < 16; nt++) {
            uint4 b = t2p[(kt * 16 + nt) * 32 + lane];
            mma_bf16(acc[nt], ah0, ah1, ah2, ah3, b.x, b.y);
            mma_bf16(acc[nt], ah0, ah1, ah2, ah3, b.z, b.w);
            mma_bf16(acc[nt], al0, al1, al2, al3, b.x, b.y);
        }
    }

    // ---- final epilogue: bias2, fp32 store, fused per-column BN statistics ----
    int row0 = base + m0 + (lane >> 2);
    bool r0v = row0 < M, r1v = (row0 + 8) < M;
#pragma unroll
    for (int nt = 0; nt < 16; nt++) {
        int n0 = nt * 8 + (lane & 3) * 2;
        float bb0 = bias2[n0], bb1 = bias2[n0 + 1];
        float v0 = acc[nt][0] + bb0, v1 = acc[nt][1] + bb1;
        float v2 = acc[nt][2] + bb0, v3 = acc[nt][3] + bb1;
        if (r0v)
            *reinterpret_cast<float2*>(C + (size_t)row0 * 128 + n0) = make_float2(v0, v1);
        if (r1v)
            *reinterpret_cast<float2*>(C + (size_t)(row0 + 8) * 128 + n0) = make_float2(v2, v3);

        float s0 = (r0v ? v0 : 0.f) + (r1v ? v2 : 0.f);
        float s1 = (r0v ? v1 : 0.f) + (r1v ? v3 : 0.f);
        float q0 = (r0v ? v0 * v0 : 0.f) + (r1v ? v2 * v2 : 0.f);
        float q1 = (r0v ? v1 * v1 : 0.f) + (r1v ? v3 * v3 : 0.f);
#pragma unroll
        for (int o = 4; o < 32; o <<= 1) {
            s0 += __shfl_xor_sync(0xffffffffu, s0, o);
            s1 += __shfl_xor_sync(0xffffffffu, s1, o);
            q0 += __shfl_xor_sync(0xffffffffu, q0, o);
            q1 += __shfl_xor_sync(0xffffffffu, q1, o);
        }
        if ((lane >> 2) == 0) {   // lanes 0..3, distinct n0 per lane
            atomicAdd(&Ssm[n0], s0);     atomicAdd(&Ssm[n0 + 1], s1);
            atomicAdd(&Qsm[n0], q0);     atomicAdd(&Qsm[n0 + 1], q1);
        }
    }
    __syncthreads();
    if (t < 128) {
        atomicAdd(&gsum[t], Ssm[t]);
        atomicAdd(&gsq[t],  Qsm[t]);
    }
}

// ---------------- BN coefficient computation (1 block, 128 threads) -------------
__global__ void bn_coef_kernel(const float* __restrict__ sum,
                               const float* __restrict__ sq,
                               const float* __restrict__ gamma,
                               const float* __restrict__ beta,
                               float* __restrict__ scale,
                               float* __restrict__ shift) {
    int c = threadIdx.x;
    const float invN = 1.0f / (float)N_NODES;
    float mean = sum[c] * invN;
    float var  = fmaxf(sq[c] * invN - mean * mean, 0.f);
    float sc   = gamma[c] * rsqrtf(var + BN_EPS);
    scale[c] = sc;
    shift[c] = beta[c] - mean * sc;
}

// ---------------- edge scatter-add (plain): agg[dst] += X[src] ------------------
__global__ void scatter_kernel(const float* __restrict__ X,
                               const int* __restrict__ ei,
                               float* __restrict__ agg) {
    int widx = (int)(((size_t)blockIdx.x * blockDim.x + threadIdx.x) >> 5);
    int lane = threadIdx.x & 31;
    if (widx >= N_EDGES) return;
    int s = ei[widx];
    int d = ei[N_EDGES + widx];
    float4 v = reinterpret_cast<const float4*>(X + (size_t)s * F)[lane];
    atomicAdd(reinterpret_cast<float4*>(agg + (size_t)d * F) + lane, v);
}

// ---------------- edge scatter-add with on-the-fly BN+ReLU of the source -------
__global__ void scatter_bn_kernel(const float* __restrict__ X,
                                  const int* __restrict__ ei,
                                  float* __restrict__ agg,
                                  const float* __restrict__ scale,
                                  const float* __restrict__ shift) {
    int widx = (int)(((size_t)blockIdx.x * blockDim.x + threadIdx.x) >> 5);
    int lane = threadIdx.x & 31;
    if (widx >= N_EDGES) return;
    float4 sc = reinterpret_cast<const float4*>(scale)[lane];   // L1-resident
    float4 sh = reinterpret_cast<const float4*>(shift)[lane];
    int s = ei[widx];
    int d = ei[N_EDGES + widx];
    float4 v = reinterpret_cast<const float4*>(X + (size_t)s * F)[lane];
    v.x = fmaxf(v.x * sc.x + sh.x, 0.f);
    v.y = fmaxf(v.y * sc.y + sh.y, 0.f);
    v.z = fmaxf(v.z * sc.z + sh.z, 0.f);
    v.w = fmaxf(v.w * sc.w + sh.w, 0.f);
    atomicAdd(reinterpret_cast<float4*>(agg + (size_t)d * F) + lane, v);
}

// ---------------- fused BN2 + ReLU + segmented pool + counts (batch sorted) -----
#define POOL_CHUNK 512
__global__ void pool_kernel(const float* __restrict__ H,
                            const float* __restrict__ scale,
                            const float* __restrict__ shift,
                            const int* __restrict__ batch) {
    const int c = threadIdx.x;   // blockDim = 128
    float sc = scale[c], sh = shift[c];

    int r0 = blockIdx.x * POOL_CHUNK;
    if (r0 >= N_NODES) return;
    int r1 = min(r0 + POOL_CHUNK, N_NODES);

    int g = batch[r0];
    float acc = 0.f;
    int cnt = 0;
    for (int r = r0; r < r1; r++) {
        int gg = batch[r];
        if (gg != g) {
            atomicAdd(&g_pooled[g * F + c], acc);
            if (c == 0) atomicAdd(&g_counts[g], (float)cnt);
            acc = 0.f; cnt = 0; g = gg;
        }
        acc += fmaxf(H[(size_t)r * F + c] * sc + sh, 0.f);
        cnt++;
    }
    atomicAdd(&g_pooled[g * F + c], acc);
    if (c == 0) atomicAdd(&g_counts[g], (float)cnt);
}

// ---------------- head: mean-pool divide + linear + log_softmax ----------------
__global__ void head_kernel(const float* __restrict__ Wlin,
                            const float* __restrict__ blin,
                            float* __restrict__ out) {
    __shared__ float Ws[F * NUM_CLASSES];
    int t = threadIdx.x;   // blockDim = 128, one thread per graph
    for (int i = t; i < F * NUM_CLASSES; i += 128) Ws[i] = Wlin[i];
    __syncthreads();

    int g = t;
    float inv = 1.0f / fmaxf(g_counts[g], 1.0f);
    float logit[NUM_CLASSES];
#pragma unroll
    for (int j = 0; j < NUM_CLASSES; j++) logit[j] = blin[j];
    for (int c = 0; c < F; c++) {
        float p = g_pooled[g * F + c] * inv;
#pragma unroll
        for (int j = 0; j < NUM_CLASSES; j++)
            logit[j] += p * Ws[c * NUM_CLASSES + j];
    }
    float m = logit[0];
#pragma unroll
    for (int j = 1; j < NUM_CLASSES; j++) m = fmaxf(m, logit[j]);
    float se = 0.f;
#pragma unroll
    for (int j = 0; j < NUM_CLASSES; j++) se += expf(logit[j] - m);
    float lse = logf(se);
#pragma unroll
    for (int j = 0; j < NUM_CLASSES; j++)
        out[g * NUM_CLASSES + j] = logit[j] - m - lse;
}

// ================================================================================
extern "C" void kernel_launch(void* const* d_in, const int* in_sizes, int n_in,
                              void* d_out, int out_size) {
    const float* x     = (const float*)d_in[0];
    const int*   ei    = (const int*)d_in[1];
    const int*   batch = (const int*)d_in[2];
    const float* W1a = (const float*)d_in[3];
    const float* b1a = (const float*)d_in[4];
    const float* W1b = (const float*)d_in[5];
    const float* b1b = (const float*)d_in[6];
    const float* gamma1 = (const float*)d_in[7];
    const float* beta1  = (const float*)d_in[8];
    const float* W2a = (const float*)d_in[9];
    const float* b2a = (const float*)d_in[10];
    const float* W2b = (const float*)d_in[11];
    const float* b2b = (const float*)d_in[12];
    const float* gamma2 = (const float*)d_in[13];
    const float* beta2  = (const float*)d_in[14];
    const float* Wlin = (const float*)d_in[15];
    const float* blin = (const float*)d_in[16];
    float* out = (float*)d_out;

    float *pA, *pB, *pC, *pSum1, *pSq1, *pSum2, *pSq2;
    float *pScale1, *pShift1, *pScale2, *pShift2;
    uint4 *pWP;
    cudaGetSymbolAddress((void**)&pA, g_bufA);
    cudaGetSymbolAddress((void**)&pB, g_bufB);
    cudaGetSymbolAddress((void**)&pC, g_bufC);
    cudaGetSymbolAddress((void**)&pSum1, g_sum1);
    cudaGetSymbolAddress((void**)&pSq1,  g_sq1);
    cudaGetSymbolAddress((void**)&pSum2, g_sum2);
    cudaGetSymbolAddress((void**)&pSq2,  g_sq2);
    cudaGetSymbolAddress((void**)&pScale1, g_scale1);
    cudaGetSymbolAddress((void**)&pShift1, g_shift1);
    cudaGetSymbolAddress((void**)&pScale2, g_scale2);
    cudaGetSymbolAddress((void**)&pShift2, g_shift2);
    cudaGetSymbolAddress((void**)&pWP, g_wtabP);

    static int smem_set = 0;
    if (!smem_set) {
        cudaFuncSetAttribute(mlp_kernel,
                             cudaFuncAttributeMaxDynamicSharedMemorySize, MLP_SMEM);
        smem_set = 1;
    }

    const int M = N_NODES;
    const int mlpBlocks = (M + 127) / 128;
    const int scatterBlocks = (N_EDGES * 32) / 256;
    const size_t bufBytes = (size_t)N_NODES * F * sizeof(float);

    // prep: zero accumulators, pack weight tables, zero agg1
    zero_small_kernel<<<64, 256>>>();
    prep_w_all_kernel<<<64, 256>>>(W1a, W1b, W2a, W2b);
    cudaMemsetAsync(pA, 0, bufBytes);

    // ---- layer 1: agg1(scatter part) -> bufA ; MLP1 adds +x during staging
    scatter_kernel<<<scatterBlocks, 256>>>(x, ei, pA);
    mlp_kernel<<<mlpBlocks, 256, MLP_SMEM>>>(
        pA, x, nullptr, nullptr, pA,
        pWP + 0 * 4096, pWP + 1 * 4096,
        b1a, b1b, pSum1, pSq1, M);
    bn_coef_kernel<<<1, 128>>>(pSum1, pSq1, gamma1, beta1, pScale1, pShift1);

    // ---- layer 2: scatter of BN1(h1) -> bufC ; MLP2 adds +BN1(h1) during staging
    cudaMemsetAsync(pC, 0, bufBytes);
    scatter_bn_kernel<<<scatterBlocks, 256>>>(pA, ei, pC, pScale1, pShift1);
    mlp_kernel<<<mlpBlocks, 256, MLP_SMEM>>>(
        pC, pA, pScale1, pShift1, pB,
        pWP + 2 * 4096, pWP + 3 * 4096,
        b2a, b2b, pSum2, pSq2, M);
    bn_coef_kernel<<<1, 128>>>(pSum2, pSq2, gamma2, beta2, pScale2, pShift2);

    // ---- pooling (BN2+ReLU on the fly, fused counts) + head
    pool_kernel<<<(N_NODES + POOL_CHUNK - 1) / POOL_CHUNK, 128>>>(
        pB, pScale2, pShift2, batch);
    head_kernel<<<1, 128>>>(Wlin, blin, out);
}

// round 10
// speedup vs baseline: 1.0942x; 1.0821x over previous
#include <cuda_runtime.h>
#include <cuda_bf16.h>
#include <cstdint>
#include <cstddef>

#define N_NODES     100000
#define N_EDGES     800000
#define F           128
#define NUM_GRAPHS  128
#define NUM_CLASSES 10
#define BN_EPS      1e-5f

// ---------------- scratch (static device globals; no allocation) ----------------
__device__ float g_bufA[(size_t)N_NODES * F];   // 51.2 MB
__device__ float g_bufB[(size_t)N_NODES * F];   // 51.2 MB
__device__ float g_bufC[(size_t)N_NODES * F];   // 51.2 MB
__device__ float g_sum1[F];
__device__ float g_sq1[F];
__device__ float g_sum2[F];
__device__ float g_sq2[F];
__device__ float g_scale1[F];
__device__ float g_shift1[F];
__device__ float g_scale2[F];
__device__ float g_shift2[F];
__device__ float g_pooled[NUM_GRAPHS * F];
__device__ float g_counts[NUM_GRAPHS];
// packed bf16 mma B-fragments: per (matrix, kt*16+nt, lane) one uint4 {h0,h1,l0,l1}
__device__ uint4 g_wtabP[4][4096];

// ---------------- zero the small accumulators (every replay) --------------------
__global__ void zero_small_kernel() {
    int t = blockIdx.x * blockDim.x + threadIdx.x;
    if (t < F) {
        g_sum1[t] = 0.f; g_sq1[t] = 0.f;
        g_sum2[t] = 0.f; g_sq2[t] = 0.f;
    }
    if (t < NUM_GRAPHS) g_counts[t] = 0.f;
    for (int i = t; i < NUM_GRAPHS * F; i += blockDim.x * gridDim.x)
        g_pooled[i] = 0.f;
}

// ---------------- bf16 split helpers -------------------------------------------
__device__ __forceinline__ uint32_t pk2(__nv_bfloat16 a, __nv_bfloat16 b) {
    return (uint32_t)__bfloat16_as_ushort(b) << 16 | (uint32_t)__bfloat16_as_ushort(a);
}
__device__ __forceinline__ void split_pair(float x, float y,
                                           uint32_t& hi, uint32_t& lo) {
    __nv_bfloat16 hx = __float2bfloat16_rn(x);
    __nv_bfloat16 hy = __float2bfloat16_rn(y);
    float rx = x - __bfloat162float(hx);
    float ry = y - __bfloat162float(hy);
    hi = pk2(hx, hy);
    lo = pk2(__float2bfloat16_rn(rx), __float2bfloat16_rn(ry));
}

// ---------------- prep: pack all 4 W matrices into packed uint4 fragment tables -
__global__ void prep_w_all_kernel(const float* __restrict__ Wa,
                                  const float* __restrict__ Wb,
                                  const float* __restrict__ Wc,
                                  const float* __restrict__ Wd) {
    int gid   = blockIdx.x * blockDim.x + threadIdx.x;   // 0..16383
    int which = gid >> 12;
    int tid   = gid & 4095;
    const float* W = which == 0 ? Wa : which == 1 ? Wb : which == 2 ? Wc : Wd;
    int lane = tid & 31;
    int e    = tid >> 5;
    int nt   = e & 15;
    int kt   = e >> 4;
    int n  = nt * 8 + (lane >> 2);
    int k0 = kt * 16 + (lane & 3) * 2;
    uint32_t h0, l0, h1, l1;
    split_pair(W[k0 * 128 + n],       W[(k0 + 1) * 128 + n], h0, l0);
    split_pair(W[(k0 + 8) * 128 + n], W[(k0 + 9) * 128 + n], h1, l1);
    g_wtabP[which][tid] = make_uint4(h0, h1, l0, l1);
}

// ---------------- mma wrapper ---------------------------------------------------
__device__ __forceinline__ void mma_bf16(float c[4],
                                         uint32_t a0, uint32_t a1, uint32_t a2, uint32_t a3,
                                         uint32_t b0, uint32_t b1) {
    asm volatile(
        "mma.sync.aligned.m16n8k16.row.col.f32.bf16.bf16.f32 "
        "{%0,%1,%2,%3}, {%4,%5,%6,%7}, {%8,%9}, {%0,%1,%2,%3};"
        : "+f"(c[0]), "+f"(c[1]), "+f"(c[2]), "+f"(c[3])
        : "r"(a0), "r"(a1), "r"(a2), "r"(a3), "r"(b0), "r"(b1));
}

// ---------------- fused MLP -----------------------------------------------------
// Warp tile 32 rows x 64 cols: warp w -> rowGroup w>>1 (rows 32g..32g+31, two m16
// tiles), colHalf w&1 (nt base 8*(w&1)). Each B uint4 feeds 6 mma (2 row tiles).
#define SA 68   // smem row stride in 32-bit words
#define MLP_SMEM (2 * 128 * SA * 4 + 256 * 4)   // A tiles + 256-float stats region
__global__ void __launch_bounds__(256, 2)
mlp_kernel(const float* __restrict__ Ain, const float* __restrict__ addSrc,
           const float* __restrict__ bnScale, const float* __restrict__ bnShift,
           float* __restrict__ C,
           const uint4* __restrict__ t1p, const uint4* __restrict__ t2p,
           const float* __restrict__ bias1, const float* __restrict__ bias2,
           float* __restrict__ gsum, float* __restrict__ gsq,
           int M) {
    extern __shared__ uint32_t sm[];
    uint32_t* Ahi = sm;                 // 128 * 68 words
    uint32_t* Alo = sm + 128 * SA;
    float*    Ssm = reinterpret_cast<float*>(sm + 2 * 128 * SA);  // [128] sums
    float*    Qsm = Ssm + 128;                                    // [128] sqs

    const int t    = threadIdx.x;
    const int lane = t & 31;
    const int w    = t >> 5;
    const int base = blockIdx.x * 128;

    if (t < 256) { Ssm[t] = 0.f; }   // zeros both Ssm and Qsm (256 contiguous)

    // ---- stage A tile: (Ain + addSrc[BN]) fp32 -> bf16 hi/lo smem --------------
    {
        int r    = t >> 1;            // row 0..127
        int half = t & 1;             // 64-col half
        int grow = base + r;
        bool valid = grow < M;
        const float4* src = valid
            ? reinterpret_cast<const float4*>(Ain + (size_t)grow * 128 + half * 64)
            : nullptr;
        const float4* add = valid
            ? reinterpret_cast<const float4*>(addSrc + (size_t)grow * 128 + half * 64)
            : nullptr;
        const float4* sc4 = bnScale
            ? reinterpret_cast<const float4*>(bnScale) + half * 16 : nullptr;
        const float4* sh4 = bnShift
            ? reinterpret_cast<const float4*>(bnShift) + half * 16 : nullptr;
        uint32_t* dh = Ahi + r * SA + half * 32;
        uint32_t* dl = Alo + r * SA + half * 32;
#pragma unroll
        for (int i = 0; i < 16; i++) {
            float4 v = make_float4(0.f, 0.f, 0.f, 0.f);
            if (valid) {
                float4 s = src[i];
                float4 a = add[i];
                if (sc4) {
                    float4 sc = sc4[i], sh = sh4[i];
                    a.x = fmaxf(a.x * sc.x + sh.x, 0.f);
                    a.y = fmaxf(a.y * sc.y + sh.y, 0.f);
                    a.z = fmaxf(a.z * sc.z + sh.z, 0.f);
                    a.w = fmaxf(a.w * sc.w + sh.w, 0.f);
                }
                v = make_float4(s.x + a.x, s.y + a.y, s.z + a.z, s.w + a.w);
            }
            uint32_t h0, l0, h1, l1;
            split_pair(v.x, v.y, h0, l0);
            split_pair(v.z, v.w, h1, l1);
            *reinterpret_cast<uint2*>(&dh[i * 2]) = make_uint2(h0, h1);
            *reinterpret_cast<uint2*>(&dl[i * 2]) = make_uint2(l0, l1);
        }
    }
    __syncthreads();

    const int g      = w >> 1;              // row group 0..3
    const int ntBase = (w & 1) * 8;         // column half
    const int mBase  = g * 32;
    const int ar0    = (mBase + (lane >> 2)) * SA + (lane & 3);  // rowtile 0 frag base
    const int ar1    = ar0 + 16 * SA;                            // rowtile 1

    float acc0[8][4], acc1[8][4];
#pragma unroll
    for (int nt = 0; nt < 8; nt++)
#pragma unroll
        for (int i = 0; i < 4; i++) { acc0[nt][i] = 0.f; acc1[nt][i] = 0.f; }

    // ================= GEMM 1 =================
#pragma unroll
    for (int kt = 0; kt < 8; kt++) {
        int wp0 = ar0 + kt * 8;
        int wp1 = ar1 + kt * 8;
        uint32_t xh0 = Ahi[wp0],     xh1 = Ahi[wp0 + 8 * SA];
        uint32_t xh2 = Ahi[wp0 + 4], xh3 = Ahi[wp0 + 8 * SA + 4];
        uint32_t xl0 = Alo[wp0],     xl1 = Alo[wp0 + 8 * SA];
        uint32_t xl2 = Alo[wp0 + 4], xl3 = Alo[wp0 + 8 * SA + 4];
        uint32_t yh0 = Ahi[wp1],     yh1 = Ahi[wp1 + 8 * SA];
        uint32_t yh2 = Ahi[wp1 + 4], yh3 = Ahi[wp1 + 8 * SA + 4];
        uint32_t yl0 = Alo[wp1],     yl1 = Alo[wp1 + 8 * SA];
        uint32_t yl2 = Alo[wp1 + 4], yl3 = Alo[wp1 + 8 * SA + 4];
#pragma unroll
        for (int nt = 0; nt < 8; nt++) {
            uint4 b = t1p[(kt * 16 + ntBase + nt) * 32 + lane];
            mma_bf16(acc0[nt], xh0, xh1, xh2, xh3, b.x, b.y);   // hi*hi
            mma_bf16(acc1[nt], yh0, yh1, yh2, yh3, b.x, b.y);
            mma_bf16(acc0[nt], xh0, xh1, xh2, xh3, b.z, b.w);   // hi*lo
            mma_bf16(acc1[nt], yh0, yh1, yh2, yh3, b.z, b.w);
            mma_bf16(acc0[nt], xl0, xl1, xl2, xl3, b.x, b.y);   // lo*hi
            mma_bf16(acc1[nt], yl0, yl1, yl2, yl3, b.x, b.y);
        }
    }
    __syncthreads();

    // ---- mid epilogue: bias1 + relu, re-split t1 into the same smem tile ----
#pragma unroll
    for (int nt = 0; nt < 8; nt++) {
        int ntg = ntBase + nt;
        int n0  = ntg * 8 + (lane & 3) * 2;
        float bb0 = bias1[n0], bb1 = bias1[n0 + 1];
        int word0 = (mBase + (lane >> 2)) * SA + ntg * 4 + (lane & 3);
#pragma unroll
        for (int rt = 0; rt < 2; rt++) {
            float (&a)[4] = rt ? acc1[nt] : acc0[nt];
            int word = word0 + rt * 16 * SA;
            float v0 = fmaxf(a[0] + bb0, 0.f);
            float v1 = fmaxf(a[1] + bb1, 0.f);
            float v2 = fmaxf(a[2] + bb0, 0.f);
            float v3 = fmaxf(a[3] + bb1, 0.f);
            uint32_t h, l;
            split_pair(v0, v1, h, l);
            Ahi[word] = h;  Alo[word] = l;
            split_pair(v2, v3, h, l);
            Ahi[word + 8 * SA] = h;  Alo[word + 8 * SA] = l;
            a[0] = a[1] = a[2] = a[3] = 0.f;
        }
    }
    __syncthreads();

    // ================= GEMM 2 =================
#pragma unroll
    for (int kt = 0; kt < 8; kt++) {
        int wp0 = ar0 + kt * 8;
        int wp1 = ar1 + kt * 8;
        uint32_t xh0 = Ahi[wp0],     xh1 = Ahi[wp0 + 8 * SA];
        uint32_t xh2 = Ahi[wp0 + 4], xh3 = Ahi[wp0 + 8 * SA + 4];
        uint32_t xl0 = Alo[wp0],     xl1 = Alo[wp0 + 8 * SA];
        uint32_t xl2 = Alo[wp0 + 4], xl3 = Alo[wp0 + 8 * SA + 4];
        uint32_t yh0 = Ahi[wp1],     yh1 = Ahi[wp1 + 8 * SA];
        uint32_t yh2 = Ahi[wp1 + 4], yh3 = Ahi[wp1 + 8 * SA + 4];
        uint32_t yl0 = Alo[wp1],     yl1 = Alo[wp1 + 8 * SA];
        uint32_t yl2 = Alo[wp1 + 4], yl3 = Alo[wp1 + 8 * SA + 4];
#pragma unroll
        for (int nt = 0; nt < 8; nt++) {
            uint4 b = t2p[(kt * 16 + ntBase + nt) * 32 + lane];
            mma_bf16(acc0[nt], xh0, xh1, xh2, xh3, b.x, b.y);
            mma_bf16(acc1[nt], yh0, yh1, yh2, yh3, b.x, b.y);
            mma_bf16(acc0[nt], xh0, xh1, xh2, xh3, b.z, b.w);
            mma_bf16(acc1[nt], yh0, yh1, yh2, yh3, b.z, b.w);
            mma_bf16(acc0[nt], xl0, xl1, xl2, xl3, b.x, b.y);
            mma_bf16(acc1[nt], yl0, yl1, yl2, yl3, b.x, b.y);
        }
    }

    // ---- final epilogue: bias2, fp32 store, fused per-column BN statistics ----
#pragma unroll
    for (int nt = 0; nt < 8; nt++) {
        int ntg = ntBase + nt;
        int n0  = ntg * 8 + (lane & 3) * 2;
        float bb0 = bias2[n0], bb1 = bias2[n0 + 1];
        float S0 = 0.f, S1 = 0.f, Q0 = 0.f, Q1 = 0.f;
#pragma unroll
        for (int rt = 0; rt < 2; rt++) {
            float (&a)[4] = rt ? acc1[nt] : acc0[nt];
            int row0 = base + mBase + rt * 16 + (lane >> 2);
            bool r0v = row0 < M, r1v = (row0 + 8) < M;
            float v0 = a[0] + bb0, v1 = a[1] + bb1;
            float v2 = a[2] + bb0, v3 = a[3] + bb1;
            if (r0v)
                *reinterpret_cast<float2*>(C + (size_t)row0 * 128 + n0) = make_float2(v0, v1);
            if (r1v)
                *reinterpret_cast<float2*>(C + (size_t)(row0 + 8) * 128 + n0) = make_float2(v2, v3);
            S0 += (r0v ? v0 : 0.f) + (r1v ? v2 : 0.f);
            S1 += (r0v ? v1 : 0.f) + (r1v ? v3 : 0.f);
            Q0 += (r0v ? v0 * v0 : 0.f) + (r1v ? v2 * v2 : 0.f);
            Q1 += (r0v ? v1 * v1 : 0.f) + (r1v ? v3 * v3 : 0.f);
        }
#pragma unroll
        for (int o = 4; o < 32; o <<= 1) {
            S0 += __shfl_xor_sync(0xffffffffu, S0, o);
            S1 += __shfl_xor_sync(0xffffffffu, S1, o);
            Q0 += __shfl_xor_sync(0xffffffffu, Q0, o);
            Q1 += __shfl_xor_sync(0xffffffffu, Q1, o);
        }
        if ((lane >> 2) == 0) {   // lanes 0..3, distinct n0 per lane
            atomicAdd(&Ssm[n0], S0);     atomicAdd(&Ssm[n0 + 1], S1);
            atomicAdd(&Qsm[n0], Q0);     atomicAdd(&Qsm[n0 + 1], Q1);
        }
    }
    __syncthreads();
    if (t < 128) {
        atomicAdd(&gsum[t], Ssm[t]);
        atomicAdd(&gsq[t],  Qsm[t]);
    }
}

// ---------------- BN coefficient computation (1 block, 128 threads) -------------
__global__ void bn_coef_kernel(const float* __restrict__ sum,
                               const float* __restrict__ sq,
                               const float* __restrict__ gamma,
                               const float* __restrict__ beta,
                               float* __restrict__ scale,
                               float* __restrict__ shift) {
    int c = threadIdx.x;
    const float invN = 1.0f / (float)N_NODES;
    float mean = sum[c] * invN;
    float var  = fmaxf(sq[c] * invN - mean * mean, 0.f);
    float sc   = gamma[c] * rsqrtf(var + BN_EPS);
    scale[c] = sc;
    shift[c] = beta[c] - mean * sc;
}

// ---------------- edge scatter-add (plain): agg[dst] += X[src] ------------------
__global__ void scatter_kernel(const float* __restrict__ X,
                               const int* __restrict__ ei,
                               float* __restrict__ agg) {
    int widx = (int)(((size_t)blockIdx.x * blockDim.x + threadIdx.x) >> 5);
    int lane = threadIdx.x & 31;
    if (widx >= N_EDGES) return;
    int s = ei[widx];
    int d = ei[N_EDGES + widx];
    float4 v = reinterpret_cast<const float4*>(X + (size_t)s * F)[lane];
    atomicAdd(reinterpret_cast<float4*>(agg + (size_t)d * F) + lane, v);
}

// ---------------- edge scatter-add with on-the-fly BN+ReLU of the source -------
__global__ void scatter_bn_kernel(const float* __restrict__ X,
                                  const int* __restrict__ ei,
                                  float* __restrict__ agg,
                                  const float* __restrict__ scale,
                                  const float* __restrict__ shift) {
    int widx = (int)(((size_t)blockIdx.x * blockDim.x + threadIdx.x) >> 5);
    int lane = threadIdx.x & 31;
    if (widx >= N_EDGES) return;
    float4 sc = reinterpret_cast<const float4*>(scale)[lane];   // L1-resident
    float4 sh = reinterpret_cast<const float4*>(shift)[lane];
    int s = ei[widx];
    int d = ei[N_EDGES + widx];
    float4 v = reinterpret_cast<const float4*>(X + (size_t)s * F)[lane];
    v.x = fmaxf(v.x * sc.x + sh.x, 0.f);
    v.y = fmaxf(v.y * sc.y + sh.y, 0.f);
    v.z = fmaxf(v.z * sc.z + sh.z, 0.f);
    v.w = fmaxf(v.w * sc.w + sh.w, 0.f);
    atomicAdd(reinterpret_cast<float4*>(agg + (size_t)d * F) + lane, v);
}

// ---------------- fused BN2 + ReLU + segmented pool + counts (batch sorted) -----
#define POOL_CHUNK 512
__global__ void pool_kernel(const float* __restrict__ H,
                            const float* __restrict__ scale,
                            const float* __restrict__ shift,
                            const int* __restrict__ batch) {
    const int c = threadIdx.x;   // blockDim = 128
    float sc = scale[c], sh = shift[c];

    int r0 = blockIdx.x * POOL_CHUNK;
    if (r0 >= N_NODES) return;
    int r1 = min(r0 + POOL_CHUNK, N_NODES);

    int g = batch[r0];
    float acc = 0.f;
    int cnt = 0;
    for (int r = r0; r < r1; r++) {
        int gg = batch[r];
        if (gg != g) {
            atomicAdd(&g_pooled[g * F + c], acc);
            if (c == 0) atomicAdd(&g_counts[g], (float)cnt);
            acc = 0.f; cnt = 0; g = gg;
        }
        acc += fmaxf(H[(size_t)r * F + c] * sc + sh, 0.f);
        cnt++;
    }
    atomicAdd(&g_pooled[g * F + c], acc);
    if (c == 0) atomicAdd(&g_counts[g], (float)cnt);
}

// ---------------- head: mean-pool divide + linear + log_softmax ----------------
__global__ void head_kernel(const float* __restrict__ Wlin,
                            const float* __restrict__ blin,
                            float* __restrict__ out) {
    __shared__ float Ws[F * NUM_CLASSES];
    int t = threadIdx.x;   // blockDim = 128, one thread per graph
    for (int i = t; i < F * NUM_CLASSES; i += 128) Ws[i] = Wlin[i];
    __syncthreads();

    int g = t;
    float inv = 1.0f / fmaxf(g_counts[g], 1.0f);
    float logit[NUM_CLASSES];
#pragma unroll
    for (int j = 0; j < NUM_CLASSES; j++) logit[j] = blin[j];
    for (int c = 0; c < F; c++) {
        float p = g_pooled[g * F + c] * inv;
#pragma unroll
        for (int j = 0; j < NUM_CLASSES; j++)
            logit[j] += p * Ws[c * NUM_CLASSES + j];
    }
    float m = logit[0];
#pragma unroll
    for (int j = 1; j < NUM_CLASSES; j++) m = fmaxf(m, logit[j]);
    float se = 0.f;
#pragma unroll
    for (int j = 0; j < NUM_CLASSES; j++) se += expf(logit[j] - m);
    float lse = logf(se);
#pragma unroll
    for (int j = 0; j < NUM_CLASSES; j++)
        out[g * NUM_CLASSES + j] = logit[j] - m - lse;
}

// ================================================================================
extern "C" void kernel_launch(void* const* d_in, const int* in_sizes, int n_in,
                              void* d_out, int out_size) {
    const float* x     = (const float*)d_in[0];
    const int*   ei    = (const int*)d_in[1];
    const int*   batch = (const int*)d_in[2];
    const float* W1a = (const float*)d_in[3];
    const float* b1a = (const float*)d_in[4];
    const float* W1b = (const float*)d_in[5];
    const float* b1b = (const float*)d_in[6];
    const float* gamma1 = (const float*)d_in[7];
    const float* beta1  = (const float*)d_in[8];
    const float* W2a = (const float*)d_in[9];
    const float* b2a = (const float*)d_in[10];
    const float* W2b = (const float*)d_in[11];
    const float* b2b = (const float*)d_in[12];
    const float* gamma2 = (const float*)d_in[13];
    const float* beta2  = (const float*)d_in[14];
    const float* Wlin = (const float*)d_in[15];
    const float* blin = (const float*)d_in[16];
    float* out = (float*)d_out;

    float *pA, *pB, *pC, *pSum1, *pSq1, *pSum2, *pSq2;
    float *pScale1, *pShift1, *pScale2, *pShift2;
    uint4 *pWP;
    cudaGetSymbolAddress((void**)&pA, g_bufA);
    cudaGetSymbolAddress((void**)&pB, g_bufB);
    cudaGetSymbolAddress((void**)&pC, g_bufC);
    cudaGetSymbolAddress((void**)&pSum1, g_sum1);
    cudaGetSymbolAddress((void**)&pSq1,  g_sq1);
    cudaGetSymbolAddress((void**)&pSum2, g_sum2);
    cudaGetSymbolAddress((void**)&pSq2,  g_sq2);
    cudaGetSymbolAddress((void**)&pScale1, g_scale1);
    cudaGetSymbolAddress((void**)&pShift1, g_shift1);
    cudaGetSymbolAddress((void**)&pScale2, g_scale2);
    cudaGetSymbolAddress((void**)&pShift2, g_shift2);
    cudaGetSymbolAddress((void**)&pWP, g_wtabP);

    static int smem_set = 0;
    if (!smem_set) {
        cudaFuncSetAttribute(mlp_kernel,
                             cudaFuncAttributeMaxDynamicSharedMemorySize, MLP_SMEM);
        smem_set = 1;
    }

    const int M = N_NODES;
    const int mlpBlocks = (M + 127) / 128;
    const int scatterBlocks = (N_EDGES * 32) / 256;
    const size_t bufBytes = (size_t)N_NODES * F * sizeof(float);

    // prep: zero accumulators, pack weight tables, zero agg1
    zero_small_kernel<<<64, 256>>>();
    prep_w_all_kernel<<<64, 256>>>(W1a, W1b, W2a, W2b);
    cudaMemsetAsync(pA, 0, bufBytes);

    // ---- layer 1: agg1(scatter part) -> bufA ; MLP1 adds +x during staging
    scatter_kernel<<<scatterBlocks, 256>>>(x, ei, pA);
    mlp_kernel<<<mlpBlocks, 256, MLP_SMEM>>>(
        pA, x, nullptr, nullptr, pA,
        pWP + 0 * 4096, pWP + 1 * 4096,
        b1a, b1b, pSum1, pSq1, M);
    bn_coef_kernel<<<1, 128>>>(pSum1, pSq1, gamma1, beta1, pScale1, pShift1);

    // ---- layer 2: scatter of BN1(h1) -> bufC ; MLP2 adds +BN1(h1) during staging
    cudaMemsetAsync(pC, 0, bufBytes);
    scatter_bn_kernel<<<scatterBlocks, 256>>>(pA, ei, pC, pScale1, pShift1);
    mlp_kernel<<<mlpBlocks, 256, MLP_SMEM>>>(
        pC, pA, pScale1, pShift1, pB,
        pWP + 2 * 4096, pWP + 3 * 4096,
        b2a, b2b, pSum2, pSq2, M);
    bn_coef_kernel<<<1, 128>>>(pSum2, pSq2, gamma2, beta2, pScale2, pShift2);

    // ---- pooling (BN2+ReLU on the fly, fused counts) + head
    pool_kernel<<<(N_NODES + POOL_CHUNK - 1) / POOL_CHUNK, 128>>>(
        pB, pScale2, pShift2, batch);
    head_kernel<<<1, 128>>>(Wlin, blin, out);
}